// round 13
// baseline (speedup 1.0000x reference)
#include <cuda_runtime.h>
#include <cuda_fp16.h>

#define L_PTS 256
#define WPB 4   // warps (clusters) per block

__device__ __forceinline__ float wredf(float v) {
#pragma unroll
    for (int o = 16; o; o >>= 1) v += __shfl_xor_sync(0xffffffffu, v, o);
    return v;
}
__device__ __forceinline__ int wredi(int v) {
    int r;
    asm volatile("redux.sync.add.s32 %0, %1, 0xffffffff;" : "=r"(r) : "r"(v));
    return r;
}

__global__ void __launch_bounds__(128, 9)
clust_geo_kernel(const float* __restrict__ data,
                 const int* __restrict__ clust_idx,
                 const int* __restrict__ clust_len,
                 float* __restrict__ out,
                 int n_clust)
{
    const int warp = threadIdx.x >> 5;
    const int lane = threadIdx.x & 31;
    const int c = blockIdx.x * WPB + warp;
    if (c >= n_clust) return;

    const int len = clust_len[c];

    // --- indices: 8 per lane, blocked mapping, 2 coalesced LDG.128 ---
    const int4* ci = reinterpret_cast<const int4*>(clust_idx + (size_t)c * L_PTS) + lane * 2;
    int4 i0 = ci[0];
    int4 i1 = ci[1];
    int idx[8] = { i0.x, i0.y, i0.z, i0.w, i1.x, i1.y, i1.z, i1.w };

    const int base_pt = lane * 8;
    const float4* d4 = reinterpret_cast<const float4*>(data);

    // fp16-packed point stash in REGISTERS (12 regs instead of 24)
    __half2 px2[4], py2[4], pz2[4];
    float sx = 0.f, sy = 0.f, sz = 0.f;
    float sxx = 0.f, sxy = 0.f, sxz = 0.f, syy = 0.f, syz = 0.f, szz = 0.f;
    float sv = 0.f, svv = 0.f;
    int cA = 0, cB = 0;   // packed sem counts: bins 0..2 / 3..4, 10 bits each

    // --- pass A: branchy gather (skip inactive loads) + shifted moments ---
#pragma unroll
    for (int j = 0; j < 4; j++) {
        float xA = 0.f, yA = 0.f, zA = 0.f;
        float xB = 0.f, yB = 0.f, zB = 0.f;
#pragma unroll
        for (int h = 0; h < 2; h++) {
            const int k = 2 * j + h;
            if ((base_pt + k) < len) {
                int id = idx[k];
                int a = (id * 3) >> 1;        // aligned float4 base of the 24B row
                float4 q0 = d4[a];
                float4 q1 = d4[a + 1];
                bool odd = (id & 1);
                float X = odd ? q0.z : q0.x;
                float Y = odd ? q0.w : q0.y;
                float Z = odd ? q1.x : q0.z;
                float V = odd ? q1.z : q1.x;
                float S = odd ? q1.w : q1.y;
                sx += X; sy += Y; sz += Z;
                sxx += X * X; sxy += X * Y; sxz += X * Z;
                syy += Y * Y; syz += Y * Z; szz += Z * Z;
                sv += V; svv += V * V;
                int s = (int)S;
                if (s < 3) cA += 1 << (10 * s);
                else       cB += 1 << (10 * (s - 3));
                if (h) { xB = X; yB = Y; zB = Z; }
                else   { xA = X; yA = Y; zA = Z; }
            }
        }
        px2[j] = __floats2half2_rn(xA, xB);
        py2[j] = __floats2half2_rn(yA, yB);
        pz2[j] = __floats2half2_rn(zA, zB);
    }
    sx = wredf(sx); sy = wredf(sy); sz = wredf(sz);
    sxx = wredf(sxx); sxy = wredf(sxy); sxz = wredf(sxz);
    syy = wredf(syy); syz = wredf(syz); szz = wredf(szz);
    sv = wredf(sv); svv = wredf(svv);
    cA = wredi(cA); cB = wredi(cB);

    const float n = (float)len;
    const float invn = 1.0f / n;
    const float cx = sx * invn, cy = sy * invn, cz = sz * invn;

    // shifted second moments: A = S2 - s1 * center
    const float axx = sxx - sx * cx, axy = sxy - sx * cy, axz = sxz - sx * cz;
    const float ayy = syy - sy * cy, ayz = syz - sy * cz, azz = szz - sz * cz;

    // --- analytic eigenvalues (Cardano), all lanes redundantly ---
    float q = (axx + ayy + azz) * (1.0f / 3.0f);
    float bxx = axx - q, byy = ayy - q, bzz = azz - q;
    float p1 = axy * axy + axz * axz + ayz * ayz;
    float p2 = bxx * bxx + byy * byy + bzz * bzz + 2.0f * p1;
    float w1, w2;
    if (p2 > 0.0f) {
        float p = sqrtf(p2 * (1.0f / 6.0f));
        float ip = 1.0f / p;
        float cxx = bxx * ip, cyy = byy * ip, czz = bzz * ip;
        float dxy = axy * ip, dxz = axz * ip, dyz = ayz * ip;
        float detB = cxx * (cyy * czz - dyz * dyz)
                   - dxy * (dxy * czz - dyz * dxz)
                   + dxz * (dxy * dyz - cyy * dxz);
        float r = 0.5f * detB;
        r = fminf(1.0f, fmaxf(-1.0f, r));
        float phi = acosf(r) * (1.0f / 3.0f);
        w2 = q + 2.0f * p * cosf(phi);
        float w0 = q + 2.0f * p * cosf(phi + 2.0943951023931953f);
        w1 = 3.0f * q - w0 - w2;
    } else {
        w1 = q; w2 = q;
    }

    // --- top eigenvector: largest cross product of rows of (A - w2 I) ---
    float mxx = axx - w2, myy = ayy - w2, mzz = azz - w2;
    float c0x = axy * ayz - axz * myy;
    float c0y = axz * axy - mxx * ayz;
    float c0z = mxx * myy - axy * axy;
    float c1x = axy * mzz - axz * ayz;
    float c1y = axz * axz - mxx * mzz;
    float c1z = mxx * ayz - axy * axz;
    float c2x = myy * mzz - ayz * ayz;
    float c2y = ayz * axz - axy * mzz;
    float c2z = axy * ayz - myy * axz;

    float n0 = c0x * c0x + c0y * c0y + c0z * c0z;
    float n1 = c1x * c1x + c1y * c1y + c1z * c1z;
    float n2 = c2x * c2x + c2y * c2y + c2z * c2z;
    float vx = c0x, vy = c0y, vz = c0z, nn = n0;
    if (n1 > nn) { vx = c1x; vy = c1y; vz = c1z; nn = n1; }
    if (n2 > nn) { vx = c2x; vy = c2y; vz = c2z; nn = n2; }
    if (nn > 0.0f) {
        float is = rsqrtf(nn);
        vx *= is; vy *= is; vz *= is;
    } else {
        vx = 0.0f; vy = 0.0f; vz = 1.0f;
    }

    // --- pass C: sign score from fp16 register stash (sign-only -> safe) ---
    float sc = 0.0f;
#pragma unroll
    for (int j = 0; j < 4; j++) {
        float2 xs = __half22float2(px2[j]);
        float2 ys = __half22float2(py2[j]);
        float2 zs = __half22float2(pz2[j]);
#pragma unroll
        for (int h = 0; h < 2; h++) {
            const int k = 2 * j + h;
            if ((base_pt + k) < len) {
                float X = (h ? xs.y : xs.x) - cx;
                float Y = (h ? ys.y : ys.x) - cy;
                float Z = (h ? zs.y : zs.x) - cz;
                float x0 = X * vx + Y * vy + Z * vz;
                float sq = X * X + Y * Y + Z * Z - x0 * x0;
                sc += x0 * sqrtf(fmaxf(sq, 0.0f));
            }
        }
    }
    sc = wredf(sc);

    float dirwt = (w2 == 0.0f) ? 0.0f : (1.0f - w1 / w2);
    float fac = ((sc < 0.0f) ? -1.0f : 1.0f) * dirwt;

    if (lane == 0) {
        float* o = out + (size_t)c * 19;
        float iw2 = 1.0f / w2;   // B = A / w2 exactly (DELTA = 0)
        o[0]  = cx; o[1] = cy; o[2] = cz;
        o[3]  = axx * iw2; o[4]  = axy * iw2; o[5]  = axz * iw2;
        o[6]  = axy * iw2; o[7]  = ayy * iw2; o[8]  = ayz * iw2;
        o[9]  = axz * iw2; o[10] = ayz * iw2; o[11] = azz * iw2;
        o[12] = vx * fac; o[13] = vy * fac; o[14] = vz * fac;
        o[15] = n;
        o[16] = sv * invn;
        float var = fmaxf(svv - sv * sv * invn, 0.0f) / (n - 1.0f);
        o[17] = sqrtf(var);
        int b0 = cA & 1023, b1 = (cA >> 10) & 1023, b2 = (cA >> 20) & 1023;
        int b3 = cB & 1023, b4 = (cB >> 10) & 1023;
        int best = b0, mode = 0;
        if (b1 > best) { best = b1; mode = 1; }
        if (b2 > best) { best = b2; mode = 2; }
        if (b3 > best) { best = b3; mode = 3; }
        if (b4 > best) { best = b4; mode = 4; }
        o[18] = (float)mode;
    }
}

extern "C" void kernel_launch(void* const* d_in, const int* in_sizes, int n_in,
                              void* d_out, int out_size) {
    const float* data      = (const float*)d_in[0];
    const int*   clust_idx = (const int*)d_in[1];
    const int*   clust_len = (const int*)d_in[2];
    float* out = (float*)d_out;
    int n_clust = in_sizes[2];
    int grid = (n_clust + WPB - 1) / WPB;
    clust_geo_kernel<<<grid, 128>>>(data, clust_idx, clust_len, out, n_clust);
}

// round 15
// speedup vs baseline: 1.5660x; 1.5660x over previous
#include <cuda_runtime.h>

#define L_PTS 256
// one warp per block, one cluster per warp; cache policy via createpolicy:
// table gathers evict_last (pin 48MB table in L2), idx loads evict_first

__device__ __forceinline__ float wredf(float v) {
#pragma unroll
    for (int o = 16; o; o >>= 1) v += __shfl_xor_sync(0xffffffffu, v, o);
    return v;
}
__device__ __forceinline__ int wredi(int v) {
    int r;
    asm volatile("redux.sync.add.s32 %0, %1, 0xffffffff;" : "=r"(r) : "r"(v));
    return r;
}

__device__ __forceinline__ unsigned long long mk_policy_keep() {
    unsigned long long p;
    asm volatile("createpolicy.fractional.L2::evict_last.b64 %0, 1.0;" : "=l"(p));
    return p;
}
__device__ __forceinline__ unsigned long long mk_policy_stream() {
    unsigned long long p;
    asm volatile("createpolicy.fractional.L2::evict_first.b64 %0, 1.0;" : "=l"(p));
    return p;
}
__device__ __forceinline__ float4 ldg_keep_v4f(const float4* p, unsigned long long pol) {
    float4 q;
    asm volatile("ld.global.nc.L2::cache_hint.v4.f32 {%0,%1,%2,%3}, [%4], %5;"
                 : "=f"(q.x), "=f"(q.y), "=f"(q.z), "=f"(q.w) : "l"(p), "l"(pol));
    return q;
}
__device__ __forceinline__ int4 ldg_stream_v4i(const int4* p, unsigned long long pol) {
    int4 q;
    asm volatile("ld.global.nc.L2::cache_hint.v4.s32 {%0,%1,%2,%3}, [%4], %5;"
                 : "=r"(q.x), "=r"(q.y), "=r"(q.z), "=r"(q.w) : "l"(p), "l"(pol));
    return q;
}

__global__ void __launch_bounds__(32)
clust_geo_kernel(const float* __restrict__ data,
                 const int* __restrict__ clust_idx,
                 const int* __restrict__ clust_len,
                 float* __restrict__ out,
                 int n_clust)
{
    const int lane = threadIdx.x;
    const int c = blockIdx.x;            // grid.x == n_clust

    const int len = clust_len[c];
    const unsigned long long pol_keep = mk_policy_keep();
    const unsigned long long pol_stream = mk_policy_stream();

    // --- indices: 8 per lane, blocked mapping, 2 coalesced streaming LDG.128 ---
    const int4* ci = reinterpret_cast<const int4*>(clust_idx + (size_t)c * L_PTS) + lane * 2;
    int4 i0 = ldg_stream_v4i(ci, pol_stream);
    int4 i1 = ldg_stream_v4i(ci + 1, pol_stream);
    int idx[8] = { i0.x, i0.y, i0.z, i0.w, i1.x, i1.y, i1.z, i1.w };

    const int base_pt = lane * 8;
    const float4* d4 = reinterpret_cast<const float4*>(data);

    float px[8], py[8], pz[8];
    float sx = 0.f, sy = 0.f, sz = 0.f;
    float sxx = 0.f, sxy = 0.f, sxz = 0.f, syy = 0.f, syz = 0.f, szz = 0.f;
    float sv = 0.f, svv = 0.f;
    int cA = 0, cB = 0;   // packed sem counts: bins 0..2 / 3..4, 10 bits each

    // --- pass A: branchy gather (skip inactive loads) + shifted moments ---
#pragma unroll
    for (int k = 0; k < 8; k++) {
        bool act = (base_pt + k) < len;
        float X = 0.f, Y = 0.f, Z = 0.f;
        if (act) {
            int id = idx[k];
            int a = (id * 3) >> 1;        // aligned float4 base of the 24B row
            float4 q0 = ldg_keep_v4f(d4 + a, pol_keep);
            float4 q1 = ldg_keep_v4f(d4 + a + 1, pol_keep);
            bool odd = (id & 1);
            X = odd ? q0.z : q0.x;
            Y = odd ? q0.w : q0.y;
            Z = odd ? q1.x : q0.z;
            float V = odd ? q1.z : q1.x;
            float S = odd ? q1.w : q1.y;
            sx += X; sy += Y; sz += Z;
            sxx += X * X; sxy += X * Y; sxz += X * Z;
            syy += Y * Y; syz += Y * Z; szz += Z * Z;
            sv += V; svv += V * V;
            int s = (int)S;
            if (s < 3) cA += 1 << (10 * s);
            else       cB += 1 << (10 * (s - 3));
        }
        px[k] = X; py[k] = Y; pz[k] = Z;
    }
    sx = wredf(sx); sy = wredf(sy); sz = wredf(sz);
    sxx = wredf(sxx); sxy = wredf(sxy); sxz = wredf(sxz);
    syy = wredf(syy); syz = wredf(syz); szz = wredf(szz);
    sv = wredf(sv); svv = wredf(svv);
    cA = wredi(cA); cB = wredi(cB);

    const float n = (float)len;
    const float invn = 1.0f / n;
    const float cx = sx * invn, cy = sy * invn, cz = sz * invn;

    // shifted second moments: A = S2 - s1 * center
    const float axx = sxx - sx * cx, axy = sxy - sx * cy, axz = sxz - sx * cz;
    const float ayy = syy - sy * cy, ayz = syz - sy * cz, azz = szz - sz * cz;

    // --- analytic eigenvalues (Cardano), all lanes redundantly ---
    float q = (axx + ayy + azz) * (1.0f / 3.0f);
    float bxx = axx - q, byy = ayy - q, bzz = azz - q;
    float p1 = axy * axy + axz * axz + ayz * ayz;
    float p2 = bxx * bxx + byy * byy + bzz * bzz + 2.0f * p1;
    float w1, w2;
    if (p2 > 0.0f) {
        float p = sqrtf(p2 * (1.0f / 6.0f));
        float ip = 1.0f / p;
        float cxx = bxx * ip, cyy = byy * ip, czz = bzz * ip;
        float dxy = axy * ip, dxz = axz * ip, dyz = ayz * ip;
        float detB = cxx * (cyy * czz - dyz * dyz)
                   - dxy * (dxy * czz - dyz * dxz)
                   + dxz * (dxy * dyz - cyy * dxz);
        float r = 0.5f * detB;
        r = fminf(1.0f, fmaxf(-1.0f, r));
        float phi = acosf(r) * (1.0f / 3.0f);
        w2 = q + 2.0f * p * cosf(phi);
        float w0 = q + 2.0f * p * cosf(phi + 2.0943951023931953f);
        w1 = 3.0f * q - w0 - w2;
    } else {
        w1 = q; w2 = q;
    }

    // --- top eigenvector: largest cross product of rows of (A - w2 I) ---
    float mxx = axx - w2, myy = ayy - w2, mzz = azz - w2;
    float c0x = axy * ayz - axz * myy;
    float c0y = axz * axy - mxx * ayz;
    float c0z = mxx * myy - axy * axy;
    float c1x = axy * mzz - axz * ayz;
    float c1y = axz * axz - mxx * mzz;
    float c1z = mxx * ayz - axy * axz;
    float c2x = myy * mzz - ayz * ayz;
    float c2y = ayz * axz - axy * mzz;
    float c2z = axy * ayz - myy * axz;

    float n0 = c0x * c0x + c0y * c0y + c0z * c0z;
    float n1 = c1x * c1x + c1y * c1y + c1z * c1z;
    float n2 = c2x * c2x + c2y * c2y + c2z * c2z;
    float vx = c0x, vy = c0y, vz = c0z, nn = n0;
    if (n1 > nn) { vx = c1x; vy = c1y; vz = c1z; nn = n1; }
    if (n2 > nn) { vx = c2x; vy = c2y; vz = c2z; nn = n2; }
    if (nn > 0.0f) {
        float is = rsqrtf(nn);
        vx *= is; vy *= is; vz *= is;
    } else {
        vx = 0.0f; vy = 0.0f; vz = 1.0f;
    }

    // --- pass C: sign score (register-resident points) ---
    float sc = 0.0f;
#pragma unroll
    for (int k = 0; k < 8; k++) {
        if ((base_pt + k) < len) {
            float X = px[k] - cx, Y = py[k] - cy, Z = pz[k] - cz;
            float x0 = X * vx + Y * vy + Z * vz;
            float sq = X * X + Y * Y + Z * Z - x0 * x0;
            sc += x0 * sqrtf(fmaxf(sq, 0.0f));
        }
    }
    sc = wredf(sc);

    float dirwt = (w2 == 0.0f) ? 0.0f : (1.0f - w1 / w2);
    float fac = ((sc < 0.0f) ? -1.0f : 1.0f) * dirwt;

    if (lane == 0) {
        float* o = out + (size_t)c * 19;
        float iw2 = 1.0f / w2;   // B = A / w2 exactly (DELTA = 0)
        o[0]  = cx; o[1] = cy; o[2] = cz;
        o[3]  = axx * iw2; o[4]  = axy * iw2; o[5]  = axz * iw2;
        o[6]  = axy * iw2; o[7]  = ayy * iw2; o[8]  = ayz * iw2;
        o[9]  = axz * iw2; o[10] = ayz * iw2; o[11] = azz * iw2;
        o[12] = vx * fac; o[13] = vy * fac; o[14] = vz * fac;
        o[15] = n;
        o[16] = sv * invn;
        float var = fmaxf(svv - sv * sv * invn, 0.0f) / (n - 1.0f);
        o[17] = sqrtf(var);
        int b0 = cA & 1023, b1 = (cA >> 10) & 1023, b2 = (cA >> 20) & 1023;
        int b3 = cB & 1023, b4 = (cB >> 10) & 1023;
        int best = b0, mode = 0;
        if (b1 > best) { best = b1; mode = 1; }
        if (b2 > best) { best = b2; mode = 2; }
        if (b3 > best) { best = b3; mode = 3; }
        if (b4 > best) { best = b4; mode = 4; }
        o[18] = (float)mode;
    }
}

extern "C" void kernel_launch(void* const* d_in, const int* in_sizes, int n_in,
                              void* d_out, int out_size) {
    const float* data      = (const float*)d_in[0];
    const int*   clust_idx = (const int*)d_in[1];
    const int*   clust_len = (const int*)d_in[2];
    float* out = (float*)d_out;
    int n_clust = in_sizes[2];
    clust_geo_kernel<<<n_clust, 32>>>(data, clust_idx, clust_len, out, n_clust);
}